// round 6
// baseline (speedup 1.0000x reference)
#include <cuda_runtime.h>
#include <cuda_bf16.h>
#include <math.h>
#include <cstdint>

#define HIDDEN 2048
#define N_HEADS 32
#define N_KV 4
#define HEAD_DIM 128
#define B_SZ 2
#define S_LEN 2048
#define TOKENS (B_SZ * S_LEN)            // 4096
#define QKV_DIM ((N_HEADS + 2 * N_KV) * HEAD_DIM)  // 5120
#define Q_SIZE (N_HEADS * HEAD_DIM)      // 4096
#define KV_SIZE (N_KV * HEAD_DIM)        // 512

// Scratch
__device__ float g_qkv[(size_t)TOKENS * QKV_DIM];   // ~84 MB
__device__ float g_attn[(size_t)TOKENS * Q_SIZE];   // ~67 MB

// ---------------------------------------------------------------------------
// Helpers
// ---------------------------------------------------------------------------
static __device__ __forceinline__ uint32_t smem_u32(const void* p) {
    uint32_t a;
    asm("{ .reg .u64 t; cvta.to.shared.u64 t, %1; cvt.u32.u64 %0, t; }" : "=r"(a) : "l"(p));
    return a;
}
static __device__ __forceinline__ uint32_t f2tf32(float x) {
    uint32_t r;
    asm("cvt.rna.tf32.f32 %0, %1;" : "=r"(r) : "f"(x));
    return r;
}
#define CP_ASYNC16(dst, src) \
    asm volatile("cp.async.cg.shared.global [%0], [%1], 16;" :: "r"(dst), "l"(src) : "memory")
#define CP_COMMIT() asm volatile("cp.async.commit_group;" ::: "memory")
#define CP_WAIT(n)  asm volatile("cp.async.wait_group %0;" :: "n"(n) : "memory")

// m16n8k8 tf32 mma.sync (row.col): D += A * B
static __device__ __forceinline__ void mma_tf32(
    float* c, const uint32_t* a, const uint32_t* b)
{
    asm volatile(
        "mma.sync.aligned.m16n8k8.row.col.f32.tf32.tf32.f32 "
        "{%0,%1,%2,%3}, {%4,%5,%6,%7}, {%8,%9}, {%0,%1,%2,%3};"
        : "+f"(c[0]), "+f"(c[1]), "+f"(c[2]), "+f"(c[3])
        : "r"(a[0]), "r"(a[1]), "r"(a[2]), "r"(a[3]), "r"(b[0]), "r"(b[1]));
}

// ---------------------------------------------------------------------------
// tf32 mma.sync GEMM: C[M,N] = A[M,K] * B[N,K]^T (row-major, K contiguous)
// ---------------------------------------------------------------------------
#define GBM 128
#define GBN 128
#define GBK 32
#define KPAD 40
#define STAGE_FLOATS ((GBM + GBN) * KPAD)
#define STAGE_BYTES (STAGE_FLOATS * 4)
#define GEMM_SMEM (2 * STAGE_BYTES)

__global__ __launch_bounds__(256) void gemm_tc(
    const float* __restrict__ A, const float* __restrict__ Bw,
    float* __restrict__ C, int M, int N, int K)
{
    extern __shared__ float smf[];
    const uint32_t smb = smem_u32(smf);
    const int tid = threadIdx.x;
    const int wid = tid >> 5;
    const int lane = tid & 31;
    const int group = lane >> 2;
    const int tig = lane & 3;
    const int wm = wid >> 2;
    const int wn = wid & 3;
    const int m0 = blockIdx.y * GBM;
    const int n0 = blockIdx.x * GBN;

    const int lrow = tid >> 3;
    const int lseg = tid & 7;

    float acc[4][4][4];
#pragma unroll
    for (int mt = 0; mt < 4; mt++)
#pragma unroll
        for (int nt = 0; nt < 4; nt++)
#pragma unroll
            for (int r = 0; r < 4; r++) acc[mt][nt][r] = 0.f;

    const int chunks = K / GBK;

    auto issue = [&](int c, int s) {
        const uint32_t sa = smb + s * STAGE_BYTES;
        const uint32_t sb = sa + GBM * KPAD * 4;
        const float* Ab = A + (size_t)m0 * K + (size_t)c * GBK;
        const float* Bb = Bw + (size_t)n0 * K + (size_t)c * GBK;
#pragma unroll
        for (int i = 0; i < 4; i++) {
            int row = lrow + i * 32;
            CP_ASYNC16(sa + row * (KPAD * 4) + lseg * 16,
                       Ab + (size_t)row * K + lseg * 4);
            CP_ASYNC16(sb + row * (KPAD * 4) + lseg * 16,
                       Bb + (size_t)row * K + lseg * 4);
        }
        CP_COMMIT();
    };

    issue(0, 0);

    for (int c = 0; c < chunks; c++) {
        const int s = c & 1;
        if (c + 1 < chunks) { issue(c + 1, s ^ 1); CP_WAIT(1); }
        else                { CP_WAIT(0); }
        __syncthreads();

        const float* As = smf + s * STAGE_FLOATS;
        const float* Bs = As + GBM * KPAD;

#pragma unroll
        for (int ks = 0; ks < 4; ks++) {
            const int kk = ks * 8 + 2 * tig;
            uint32_t a[4][4], b[4][2];
#pragma unroll
            for (int mt = 0; mt < 4; mt++) {
                int mr = wm * 64 + mt * 16 + group;
                float2 v0 = *(const float2*)&As[mr * KPAD + kk];
                float2 v1 = *(const float2*)&As[(mr + 8) * KPAD + kk];
                a[mt][0] = f2tf32(v0.x);
                a[mt][2] = f2tf32(v0.y);
                a[mt][1] = f2tf32(v1.x);
                a[mt][3] = f2tf32(v1.y);
            }
#pragma unroll
            for (int nt = 0; nt < 4; nt++) {
                int nr = wn * 32 + nt * 8 + group;
                float2 v = *(const float2*)&Bs[nr * KPAD + kk];
                b[nt][0] = f2tf32(v.x);
                b[nt][1] = f2tf32(v.y);
            }
#pragma unroll
            for (int mt = 0; mt < 4; mt++)
#pragma unroll
                for (int nt = 0; nt < 4; nt++)
                    mma_tf32(acc[mt][nt], a[mt], b[nt]);
        }
        __syncthreads();
    }

#pragma unroll
    for (int mt = 0; mt < 4; mt++) {
        int mr = m0 + wm * 64 + mt * 16 + group;
#pragma unroll
        for (int nt = 0; nt < 4; nt++) {
            int nc = n0 + wn * 32 + nt * 8 + 2 * tig;
            *(float2*)&C[(size_t)mr * N + nc] =
                make_float2(acc[mt][nt][0], acc[mt][nt][1]);
            *(float2*)&C[(size_t)(mr + 8) * N + nc] =
                make_float2(acc[mt][nt][2], acc[mt][nt][3]);
        }
    }
}

// ---------------------------------------------------------------------------
// Per-(token, head) RMSNorm + RoPE, in place on g_qkv.
// ---------------------------------------------------------------------------
__global__ __launch_bounds__(128) void norm_rope(
    float* __restrict__ qkv, const int* __restrict__ positions,
    const float* __restrict__ qw, const float* __restrict__ kw)
{
    const int blk = blockIdx.x;
    const int t = blk / (N_HEADS + N_KV);
    const int hh = blk % (N_HEADS + N_KV);
    float* ptr;
    const float* w;
    if (hh < N_HEADS) {
        ptr = qkv + (size_t)t * QKV_DIM + hh * HEAD_DIM;
        w = qw;
    } else {
        ptr = qkv + (size_t)t * QKV_DIM + Q_SIZE + (hh - N_HEADS) * HEAD_DIM;
        w = kw;
    }
    const int tid = threadIdx.x;
    __shared__ float xs[128];
    __shared__ float red[4];

    float x = ptr[tid];
    float ss = x * x;
#pragma unroll
    for (int o = 16; o > 0; o >>= 1) ss += __shfl_xor_sync(0xffffffffu, ss, o);
    if ((tid & 31) == 0) red[tid >> 5] = ss;
    __syncthreads();
    float tot = red[0] + red[1] + red[2] + red[3];
    float r = rsqrtf(tot * (1.0f / 128.0f) + 1e-6f);
    xs[tid] = x * r * w[tid];
    __syncthreads();

    if (tid < 64) {
        int pos = positions[t];
        double invf = exp(-(double)tid * (13.815510557964274 / 64.0));
        double ang = (double)pos * invf;
        double sd, cd;
        sincos(ang, &sd, &cd);
        float c = (float)cd, s = (float)sd;
        float x1 = xs[tid], x2 = xs[tid + 64];
        ptr[tid]      = x1 * c - x2 * s;
        ptr[tid + 64] = x2 * c + x1 * s;
    }
}

// ---------------------------------------------------------------------------
// Tensor-core flash attention (tf32 mma.sync), causal, GQA group 8.
// CTA: 256 q-rows of one (b,h), 512 threads / 16 warps; warp w owns q-rows
// [16w, 16w+16). Key tile 32, cp.async double-buffered K/V.
// Fully-masked tiles are skipped per-warp (causal warp-skip).
// ---------------------------------------------------------------------------
#define FA_QROWS 256
#define FA_KTILE 32
#define FA_QSTRIDE 136
#define FA_KSTRIDE 136
#define FA_Q_FLOATS (FA_QROWS * FA_QSTRIDE)            // 34816
#define FA_KV_FLOATS (FA_KTILE * FA_KSTRIDE)           // 4352
#define FA_SMEM ((FA_Q_FLOATS + 4 * FA_KV_FLOATS) * 4) // 208896 B

__global__ __launch_bounds__(512, 1) void flash_tc(
    const float* __restrict__ qkv, float* __restrict__ attn_out)
{
    extern __shared__ float smf[];
    float* Qs = smf;                                 // [256][136] tf32-rounded, scaled
    float* Ks[2] = { Qs + FA_Q_FLOATS, Qs + FA_Q_FLOATS + FA_KV_FLOATS };
    float* Vs[2] = { Qs + FA_Q_FLOATS + 2 * FA_KV_FLOATS,
                     Qs + FA_Q_FLOATS + 3 * FA_KV_FLOATS };
    const uint32_t smb = smem_u32(smf);
    const uint32_t ks_off[2] = { (uint32_t)(FA_Q_FLOATS * 4),
                                 (uint32_t)((FA_Q_FLOATS + FA_KV_FLOATS) * 4) };
    const uint32_t vs_off[2] = { (uint32_t)((FA_Q_FLOATS + 2 * FA_KV_FLOATS) * 4),
                                 (uint32_t)((FA_Q_FLOATS + 3 * FA_KV_FLOATS) * 4) };

    const int qi = (int)(gridDim.x - 1 - blockIdx.x);   // largest tile first
    const int bh = blockIdx.y;
    const int b = bh >> 5;
    const int h = bh & 31;
    const int kvh = h >> 3;
    const int tid = threadIdx.x;
    const int wid = tid >> 5;
    const int lane = tid & 31;
    const int group = lane >> 2;
    const int tig = lane & 3;
    const int qm0 = qi * FA_QROWS;
    const float scale = 0.08838834764831845f;

    // ---- load Q tile (scaled + tf32-rounded): 256 rows x 32 float4 ----
    const float* qbase = qkv + (size_t)(b * S_LEN + qm0) * QKV_DIM + h * HEAD_DIM;
#pragma unroll
    for (int i = 0; i < 16; i++) {
        int f = tid + i * 512;             // 0..8191 float4 units
        int row = f >> 5, c4 = f & 31;
        float4 v = *(const float4*)&qbase[(size_t)row * QKV_DIM + c4 * 4];
        float* d = &Qs[row * FA_QSTRIDE + c4 * 4];
        d[0] = __uint_as_float(f2tf32(v.x * scale));
        d[1] = __uint_as_float(f2tf32(v.y * scale));
        d[2] = __uint_as_float(f2tf32(v.z * scale));
        d[3] = __uint_as_float(f2tf32(v.w * scale));
    }

    const float* kbase = qkv + (size_t)(b * S_LEN) * QKV_DIM + Q_SIZE + kvh * HEAD_DIM;
    const float* vbase = kbase + KV_SIZE;
    const int ntiles = 8 * qi + 8;

    // issue K/V tile kt into stage s: 32 rows x 128 floats each, 512 threads
    auto issue = [&](int kt, int s) {
        const int lrow = tid >> 4;         // 0..31
        const int lseg = tid & 15;         // 16 threads per row, 2 float4 each
        const float* ksrc = kbase + (size_t)(kt * FA_KTILE + lrow) * QKV_DIM;
        const float* vsrc = vbase + (size_t)(kt * FA_KTILE + lrow) * QKV_DIM;
        uint32_t kd = smb + ks_off[s] + lrow * (FA_KSTRIDE * 4);
        uint32_t vd = smb + vs_off[s] + lrow * (FA_KSTRIDE * 4);
#pragma unroll
        for (int i = 0; i < 2; i++) {
            int c = (lseg + i * 16) * 4;   // float index: covers 0..124
            CP_ASYNC16(kd + c * 4, ksrc + c);
            CP_ASYNC16(vd + c * 4, vsrc + c);
        }
        CP_COMMIT();
    };

    issue(0, 0);
    __syncthreads();   // Q ready

    float m_i[2] = {-1e30f, -1e30f};
    float l_i[2] = {0.f, 0.f};
    float O[16][4];
#pragma unroll
    for (int nt = 0; nt < 16; nt++)
#pragma unroll
        for (int r = 0; r < 4; r++) O[nt][r] = 0.f;

    const int qrow_base = wid * 16 + group;        // warp-local q rows (+0 / +8)
    const int warp_qmax = qm0 + wid * 16 + 15;     // highest q row this warp owns

    for (int kt = 0; kt < ntiles; kt++) {
        const int s = kt & 1;
        if (kt + 1 < ntiles) { issue(kt + 1, s ^ 1); CP_WAIT(1); }
        else                 { CP_WAIT(0); }
        __syncthreads();

        // causal warp-skip: tile fully masked for this warp -> barriers only
        if (kt * FA_KTILE <= warp_qmax) {
            const float* Kst = Ks[s];
            const float* Vst = Vs[s];

            // ---- S = Q K^T : 4 n-tiles of 8 keys, 16 k-steps over d ----
            float S[4][4];
#pragma unroll
            for (int nt = 0; nt < 4; nt++)
#pragma unroll
                for (int r = 0; r < 4; r++) S[nt][r] = 0.f;

#pragma unroll
            for (int ks = 0; ks < 16; ks++) {
                const int kk = ks * 8 + 2 * tig;
                uint32_t a[4];
                {
                    float2 v0 = *(const float2*)&Qs[qrow_base * FA_QSTRIDE + kk];
                    float2 v1 = *(const float2*)&Qs[(qrow_base + 8) * FA_QSTRIDE + kk];
                    a[0] = __float_as_uint(v0.x);
                    a[1] = __float_as_uint(v1.x);
                    a[2] = __float_as_uint(v0.y);
                    a[3] = __float_as_uint(v1.y);
                }
#pragma unroll
                for (int nt = 0; nt < 4; nt++) {
                    float2 w = *(const float2*)&Kst[(nt * 8 + group) * FA_KSTRIDE + kk];
                    uint32_t bfr[2] = { f2tf32(w.x), f2tf32(w.y) };
                    mma_tf32(S[nt], a, bfr);
                }
            }

            // ---- causal mask on boundary tiles ----
            if (kt * FA_KTILE + FA_KTILE - 1 > qm0 + wid * 16) {
                const int q0 = qm0 + qrow_base;
                const int kbase_g = kt * FA_KTILE + 2 * tig;
#pragma unroll
                for (int nt = 0; nt < 4; nt++) {
                    int k0 = kbase_g + nt * 8;
                    if (k0 > q0)     S[nt][0] = -1e30f;
                    if (k0 + 1 > q0) S[nt][1] = -1e30f;
                    if (k0 > q0 + 8)     S[nt][2] = -1e30f;
                    if (k0 + 1 > q0 + 8) S[nt][3] = -1e30f;
                }
            }

            // ---- online softmax (rows r0=qrow_base, r1=+8) ----
            float mx0 = -1e30f, mx1 = -1e30f;
#pragma unroll
            for (int nt = 0; nt < 4; nt++) {
                mx0 = fmaxf(mx0, fmaxf(S[nt][0], S[nt][1]));
                mx1 = fmaxf(mx1, fmaxf(S[nt][2], S[nt][3]));
            }
            mx0 = fmaxf(mx0, __shfl_xor_sync(0xffffffffu, mx0, 1));
            mx0 = fmaxf(mx0, __shfl_xor_sync(0xffffffffu, mx0, 2));
            mx1 = fmaxf(mx1, __shfl_xor_sync(0xffffffffu, mx1, 1));
            mx1 = fmaxf(mx1, __shfl_xor_sync(0xffffffffu, mx1, 2));

            float mn0 = fmaxf(m_i[0], mx0);
            float mn1 = fmaxf(m_i[1], mx1);
            float al0 = __expf(m_i[0] - mn0);
            float al1 = __expf(m_i[1] - mn1);
            m_i[0] = mn0; m_i[1] = mn1;

            float sum0 = 0.f, sum1 = 0.f;
#pragma unroll
            for (int nt = 0; nt < 4; nt++) {
                float p0 = __expf(S[nt][0] - mn0);
                float p1 = __expf(S[nt][1] - mn0);
                float p2 = __expf(S[nt][2] - mn1);
                float p3 = __expf(S[nt][3] - mn1);
                sum0 += p0 + p1;
                sum1 += p2 + p3;
                S[nt][0] = __uint_as_float(f2tf32(p0));
                S[nt][1] = __uint_as_float(f2tf32(p1));
                S[nt][2] = __uint_as_float(f2tf32(p2));
                S[nt][3] = __uint_as_float(f2tf32(p3));
            }
            sum0 += __shfl_xor_sync(0xffffffffu, sum0, 1);
            sum0 += __shfl_xor_sync(0xffffffffu, sum0, 2);
            sum1 += __shfl_xor_sync(0xffffffffu, sum1, 1);
            sum1 += __shfl_xor_sync(0xffffffffu, sum1, 2);
            l_i[0] = l_i[0] * al0 + sum0;
            l_i[1] = l_i[1] * al1 + sum1;

#pragma unroll
            for (int nt = 0; nt < 16; nt++) {
                O[nt][0] *= al0; O[nt][1] *= al0;
                O[nt][2] *= al1; O[nt][3] *= al1;
            }

            // ---- O += P V : P fragments = S accum (k-permuted) ----
#pragma unroll
            for (int ks2 = 0; ks2 < 4; ks2++) {
                uint32_t a[4] = { __float_as_uint(S[ks2][0]), __float_as_uint(S[ks2][2]),
                                  __float_as_uint(S[ks2][1]), __float_as_uint(S[ks2][3]) };
                const int vrow = ks2 * 8 + 2 * tig;
#pragma unroll
                for (int nt = 0; nt < 16; nt++) {
                    int vcol = nt * 8 + group;
                    uint32_t bfr[2] = {
                        f2tf32(Vst[vrow * FA_KSTRIDE + vcol]),
                        f2tf32(Vst[(vrow + 1) * FA_KSTRIDE + vcol]) };
                    mma_tf32(O[nt], a, bfr);
                }
            }
        }
        __syncthreads();   // all warps done with stage s before it is re-filled
    }

    // ---- epilogue ----
    float inv0 = 1.f / l_i[0];
    float inv1 = 1.f / l_i[1];
    const size_t orow0 = (size_t)(b * S_LEN + qm0 + qrow_base) * Q_SIZE + h * HEAD_DIM;
    const size_t orow1 = orow0 + 8 * Q_SIZE;
#pragma unroll
    for (int nt = 0; nt < 16; nt++) {
        int nc = nt * 8 + 2 * tig;
        *(float2*)&attn_out[orow0 + nc] = make_float2(O[nt][0] * inv0, O[nt][1] * inv0);
        *(float2*)&attn_out[orow1 + nc] = make_float2(O[nt][2] * inv1, O[nt][3] * inv1);
    }
}

// ---------------------------------------------------------------------------
extern "C" void kernel_launch(void* const* d_in, const int* in_sizes, int n_in,
                              void* d_out, int out_size)
{
    const float* hidden    = (const float*)d_in[0];
    const int*   positions = (const int*)d_in[1];
    const float* w_qkv     = (const float*)d_in[2];
    const float* w_o       = (const float*)d_in[3];
    const float* q_norm_w  = (const float*)d_in[4];
    const float* k_norm_w  = (const float*)d_in[5];
    float* out = (float*)d_out;

    float* qkv;
    float* attn;
    cudaGetSymbolAddress((void**)&qkv, g_qkv);
    cudaGetSymbolAddress((void**)&attn, g_attn);

    cudaFuncSetAttribute(gemm_tc, cudaFuncAttributeMaxDynamicSharedMemorySize, GEMM_SMEM);
    cudaFuncSetAttribute(flash_tc, cudaFuncAttributeMaxDynamicSharedMemorySize, FA_SMEM);

    // 1) QKV projection (tf32 mma.sync)
    gemm_tc<<<dim3(QKV_DIM / GBN, TOKENS / GBM), 256, GEMM_SMEM>>>(
        hidden, w_qkv, qkv, TOKENS, QKV_DIM, HIDDEN);

    // 2) RMSNorm + RoPE
    norm_rope<<<TOKENS * (N_HEADS + N_KV), 128>>>(qkv, positions, q_norm_w, k_norm_w);

    // 3) Causal flash attention (tf32 mma.sync, 512 threads, 256-row q tiles)
    flash_tc<<<dim3(S_LEN / FA_QROWS, B_SZ * N_HEADS), 512, FA_SMEM>>>(qkv, attn);

    // 4) Output projection (tf32 mma.sync)
    gemm_tc<<<dim3(HIDDEN / GBN, TOKENS / GBM), 256, GEMM_SMEM>>>(
        attn, w_o, out, TOKENS, HIDDEN, Q_SIZE);
}

// round 8
// speedup vs baseline: 1.0832x; 1.0832x over previous
#include <cuda_runtime.h>
#include <cuda_bf16.h>
#include <math.h>
#include <cstdint>

#define HIDDEN 2048
#define N_HEADS 32
#define N_KV 4
#define HEAD_DIM 128
#define B_SZ 2
#define S_LEN 2048
#define TOKENS (B_SZ * S_LEN)            // 4096
#define QKV_DIM ((N_HEADS + 2 * N_KV) * HEAD_DIM)  // 5120
#define Q_SIZE (N_HEADS * HEAD_DIM)      // 4096
#define KV_SIZE (N_KV * HEAD_DIM)        // 512

// Scratch
__device__ float g_qkv[(size_t)TOKENS * QKV_DIM];            // ~84 MB
__device__ float g_attn[(size_t)TOKENS * Q_SIZE];            // ~67 MB
__device__ float g_vt[(size_t)B_SZ * N_KV * HEAD_DIM * S_LEN]; // 8 MB, tf32-rounded V^T

// ---------------------------------------------------------------------------
// Helpers
// ---------------------------------------------------------------------------
static __device__ __forceinline__ uint32_t smem_u32(const void* p) {
    uint32_t a;
    asm("{ .reg .u64 t; cvta.to.shared.u64 t, %1; cvt.u32.u64 %0, t; }" : "=r"(a) : "l"(p));
    return a;
}
static __device__ __forceinline__ uint32_t f2tf32(float x) {
    uint32_t r;
    asm("cvt.rna.tf32.f32 %0, %1;" : "=r"(r) : "f"(x));
    return r;
}
#define CP_ASYNC16(dst, src) \
    asm volatile("cp.async.cg.shared.global [%0], [%1], 16;" :: "r"(dst), "l"(src) : "memory")
#define CP_COMMIT() asm volatile("cp.async.commit_group;" ::: "memory")
#define CP_WAIT(n)  asm volatile("cp.async.wait_group %0;" :: "n"(n) : "memory")

// m16n8k8 tf32 mma.sync (row.col): D += A * B
static __device__ __forceinline__ void mma_tf32(
    float* c, const uint32_t* a, const uint32_t* b)
{
    asm volatile(
        "mma.sync.aligned.m16n8k8.row.col.f32.tf32.tf32.f32 "
        "{%0,%1,%2,%3}, {%4,%5,%6,%7}, {%8,%9}, {%0,%1,%2,%3};"
        : "+f"(c[0]), "+f"(c[1]), "+f"(c[2]), "+f"(c[3])
        : "r"(a[0]), "r"(a[1]), "r"(a[2]), "r"(a[3]), "r"(b[0]), "r"(b[1]));
}

// ---------------------------------------------------------------------------
// tf32 mma.sync GEMM: C[M,N] = A[M,K] * B[N,K]^T (row-major, K contiguous)
// ---------------------------------------------------------------------------
#define GBM 128
#define GBN 128
#define GBK 32
#define KPAD 40
#define STAGE_FLOATS ((GBM + GBN) * KPAD)
#define STAGE_BYTES (STAGE_FLOATS * 4)
#define GEMM_SMEM (2 * STAGE_BYTES)

__global__ __launch_bounds__(256) void gemm_tc(
    const float* __restrict__ A, const float* __restrict__ Bw,
    float* __restrict__ C, int M, int N, int K)
{
    extern __shared__ float smf[];
    const uint32_t smb = smem_u32(smf);
    const int tid = threadIdx.x;
    const int wid = tid >> 5;
    const int lane = tid & 31;
    const int group = lane >> 2;
    const int tig = lane & 3;
    const int wm = wid >> 2;
    const int wn = wid & 3;
    const int m0 = blockIdx.y * GBM;
    const int n0 = blockIdx.x * GBN;

    const int lrow = tid >> 3;
    const int lseg = tid & 7;

    float acc[4][4][4];
#pragma unroll
    for (int mt = 0; mt < 4; mt++)
#pragma unroll
        for (int nt = 0; nt < 4; nt++)
#pragma unroll
            for (int r = 0; r < 4; r++) acc[mt][nt][r] = 0.f;

    const int chunks = K / GBK;

    auto issue = [&](int c, int s) {
        const uint32_t sa = smb + s * STAGE_BYTES;
        const uint32_t sb = sa + GBM * KPAD * 4;
        const float* Ab = A + (size_t)m0 * K + (size_t)c * GBK;
        const float* Bb = Bw + (size_t)n0 * K + (size_t)c * GBK;
#pragma unroll
        for (int i = 0; i < 4; i++) {
            int row = lrow + i * 32;
            CP_ASYNC16(sa + row * (KPAD * 4) + lseg * 16,
                       Ab + (size_t)row * K + lseg * 4);
            CP_ASYNC16(sb + row * (KPAD * 4) + lseg * 16,
                       Bb + (size_t)row * K + lseg * 4);
        }
        CP_COMMIT();
    };

    issue(0, 0);

    for (int c = 0; c < chunks; c++) {
        const int s = c & 1;
        if (c + 1 < chunks) { issue(c + 1, s ^ 1); CP_WAIT(1); }
        else                { CP_WAIT(0); }
        __syncthreads();

        const float* As = smf + s * STAGE_FLOATS;
        const float* Bs = As + GBM * KPAD;

#pragma unroll
        for (int ks = 0; ks < 4; ks++) {
            const int kk = ks * 8 + 2 * tig;
            uint32_t a[4][4], b[4][2];
#pragma unroll
            for (int mt = 0; mt < 4; mt++) {
                int mr = wm * 64 + mt * 16 + group;
                float2 v0 = *(const float2*)&As[mr * KPAD + kk];
                float2 v1 = *(const float2*)&As[(mr + 8) * KPAD + kk];
                a[mt][0] = f2tf32(v0.x);
                a[mt][2] = f2tf32(v0.y);
                a[mt][1] = f2tf32(v1.x);
                a[mt][3] = f2tf32(v1.y);
            }
#pragma unroll
            for (int nt = 0; nt < 4; nt++) {
                int nr = wn * 32 + nt * 8 + group;
                float2 v = *(const float2*)&Bs[nr * KPAD + kk];
                b[nt][0] = f2tf32(v.x);
                b[nt][1] = f2tf32(v.y);
            }
#pragma unroll
            for (int mt = 0; mt < 4; mt++)
#pragma unroll
                for (int nt = 0; nt < 4; nt++)
                    mma_tf32(acc[mt][nt], a[mt], b[nt]);
        }
        __syncthreads();
    }

#pragma unroll
    for (int mt = 0; mt < 4; mt++) {
        int mr = m0 + wm * 64 + mt * 16 + group;
#pragma unroll
        for (int nt = 0; nt < 4; nt++) {
            int nc = n0 + wn * 32 + nt * 8 + 2 * tig;
            *(float2*)&C[(size_t)mr * N + nc] =
                make_float2(acc[mt][nt][0], acc[mt][nt][1]);
            *(float2*)&C[(size_t)(mr + 8) * N + nc] =
                make_float2(acc[mt][nt][2], acc[mt][nt][3]);
        }
    }
}

// ---------------------------------------------------------------------------
// Per-(token, head) RMSNorm + RoPE, in place on g_qkv.
// K heads are additionally pre-rounded to tf32 (identical to fragment-time
// rounding in the attention kernel, which now loads K raw).
// ---------------------------------------------------------------------------
__global__ __launch_bounds__(128) void norm_rope(
    float* __restrict__ qkv, const int* __restrict__ positions,
    const float* __restrict__ qw, const float* __restrict__ kw)
{
    const int blk = blockIdx.x;
    const int t = blk / (N_HEADS + N_KV);
    const int hh = blk % (N_HEADS + N_KV);
    float* ptr;
    const float* w;
    const bool is_k = (hh >= N_HEADS);
    if (!is_k) {
        ptr = qkv + (size_t)t * QKV_DIM + hh * HEAD_DIM;
        w = qw;
    } else {
        ptr = qkv + (size_t)t * QKV_DIM + Q_SIZE + (hh - N_HEADS) * HEAD_DIM;
        w = kw;
    }
    const int tid = threadIdx.x;
    __shared__ float xs[128];
    __shared__ float red[4];

    float x = ptr[tid];
    float ss = x * x;
#pragma unroll
    for (int o = 16; o > 0; o >>= 1) ss += __shfl_xor_sync(0xffffffffu, ss, o);
    if ((tid & 31) == 0) red[tid >> 5] = ss;
    __syncthreads();
    float tot = red[0] + red[1] + red[2] + red[3];
    float r = rsqrtf(tot * (1.0f / 128.0f) + 1e-6f);
    xs[tid] = x * r * w[tid];
    __syncthreads();

    if (tid < 64) {
        int pos = positions[t];
        double invf = exp(-(double)tid * (13.815510557964274 / 64.0));
        double ang = (double)pos * invf;
        double sd, cd;
        sincos(ang, &sd, &cd);
        float c = (float)cd, s = (float)sd;
        float x1 = xs[tid], x2 = xs[tid + 64];
        float o1 = x1 * c - x2 * s;
        float o2 = x2 * c + x1 * s;
        if (is_k) {
            ptr[tid]      = __uint_as_float(f2tf32(o1));
            ptr[tid + 64] = __uint_as_float(f2tf32(o2));
        } else {
            ptr[tid]      = o1;
            ptr[tid + 64] = o2;
        }
    }
}

// ---------------------------------------------------------------------------
// V transpose + tf32 round: g_vt[((b*N_KV+kvh)*HEAD_DIM + d)*S_LEN + s]
//                           = tf32(V[b][s][kvh][d])
// 32x32 tiles, 256 threads.
// ---------------------------------------------------------------------------
__global__ __launch_bounds__(256) void transpose_v(
    const float* __restrict__ qkv, float* __restrict__ vt)
{
    __shared__ float tile[32][33];
    const int sb = blockIdx.x * 32;
    int rest = blockIdx.y;                 // = b*16 + kvh*4 + dt
    const int dt = rest & 3; rest >>= 2;
    const int kvh = rest & 3; rest >>= 2;
    const int b = rest;
    const int tx = threadIdx.x & 31;
    const int ty = threadIdx.x >> 5;       // 0..7

    const float* src = qkv + (size_t)(b * S_LEN + sb) * QKV_DIM
                     + Q_SIZE + KV_SIZE + kvh * HEAD_DIM + dt * 32;
#pragma unroll
    for (int i = 0; i < 4; i++) {
        int s = ty + i * 8;
        tile[s][tx] = src[(size_t)s * QKV_DIM + tx];
    }
    __syncthreads();
    float* dst = vt + ((size_t)(b * N_KV + kvh) * HEAD_DIM + dt * 32) * S_LEN + sb;
#pragma unroll
    for (int i = 0; i < 4; i++) {
        int d = ty + i * 8;
        dst[(size_t)d * S_LEN + tx] = __uint_as_float(f2tf32(tile[tx][d]));
    }
}

// ---------------------------------------------------------------------------
// Tensor-core flash attention (tf32 mma.sync), causal, GQA group 8.
// CTA: 128 q-rows of one (b,h), 256 threads / 8 warps; warp w owns q-rows
// [16w,16w+16). Key tile 64. K (pre-rounded, row-major) and Vt (pre-rounded,
// [d][s] transposed) both cp.async double-buffered; PV B-fragments are
// contiguous LDS.64 like the K fragments. No cvt in the inner loops.
// ---------------------------------------------------------------------------
#define FA_QSTRIDE 136
#define FA_KSTRIDE 136
#define FA_VT 72
#define FA_Q_FLOATS (128 * FA_QSTRIDE)             // 17408
#define FA_K_FLOATS (64 * FA_KSTRIDE)              // 8704
#define FA_V_FLOATS (128 * FA_VT)                  // 9216
#define FA_SMEM ((FA_Q_FLOATS + 2 * FA_K_FLOATS + 2 * FA_V_FLOATS) * 4) // 212992 B

__global__ __launch_bounds__(256, 1) void flash_tc(
    const float* __restrict__ qkv, const float* __restrict__ vt,
    float* __restrict__ attn_out)
{
    extern __shared__ float smf[];
    float* Qs = smf;                                   // [128][136]
    float* Ks[2] = { Qs + FA_Q_FLOATS, Qs + FA_Q_FLOATS + FA_K_FLOATS };
    float* Vs[2] = { Qs + FA_Q_FLOATS + 2 * FA_K_FLOATS,
                     Qs + FA_Q_FLOATS + 2 * FA_K_FLOATS + FA_V_FLOATS };
    const uint32_t smb = smem_u32(smf);
    const uint32_t ks_off[2] = { (uint32_t)(FA_Q_FLOATS * 4),
                                 (uint32_t)((FA_Q_FLOATS + FA_K_FLOATS) * 4) };
    const uint32_t vs_off[2] = { (uint32_t)((FA_Q_FLOATS + 2 * FA_K_FLOATS) * 4),
                                 (uint32_t)((FA_Q_FLOATS + 2 * FA_K_FLOATS + FA_V_FLOATS) * 4) };

    const int qi = (int)(gridDim.x - 1 - blockIdx.x);   // largest tile first
    const int bh = blockIdx.y;
    const int b = bh >> 5;
    const int h = bh & 31;
    const int kvh = h >> 3;
    const int tid = threadIdx.x;
    const int wid = tid >> 5;
    const int lane = tid & 31;
    const int group = lane >> 2;
    const int tig = lane & 3;
    const int qm0 = qi * 128;
    const float scale = 0.08838834764831845f;

    // ---- load Q tile (scaled + tf32-rounded) ----
    const float* qbase = qkv + (size_t)(b * S_LEN + qm0) * QKV_DIM + h * HEAD_DIM;
#pragma unroll
    for (int i = 0; i < 16; i++) {
        int f = tid + i * 256;             // 0..4095 float4 units
        int row = f >> 5, c4 = f & 31;
        float4 v = *(const float4*)&qbase[(size_t)row * QKV_DIM + c4 * 4];
        float* d = &Qs[row * FA_QSTRIDE + c4 * 4];
        d[0] = __uint_as_float(f2tf32(v.x * scale));
        d[1] = __uint_as_float(f2tf32(v.y * scale));
        d[2] = __uint_as_float(f2tf32(v.z * scale));
        d[3] = __uint_as_float(f2tf32(v.w * scale));
    }

    const float* kbase = qkv + (size_t)(b * S_LEN) * QKV_DIM + Q_SIZE + kvh * HEAD_DIM;
    const float* vtbase = vt + (size_t)(b * N_KV + kvh) * HEAD_DIM * S_LEN;
    const int ntiles = 2 * qi + 2;

    // issue K (row-major) and Vt ([d][s]) tile kt into stage s
    auto issue = [&](int kt, int s) {
        {   // K: 64 rows x 128 floats; 4 threads/row, 8 float4 each
            const int lrow = tid >> 2;
            const int lseg = tid & 3;
            const float* ksrc = kbase + (size_t)(kt * 64 + lrow) * QKV_DIM;
            uint32_t kd = smb + ks_off[s] + lrow * (FA_KSTRIDE * 4);
#pragma unroll
            for (int i = 0; i < 8; i++) {
                int c = lseg * 4 + i * 16;
                CP_ASYNC16(kd + c * 4, ksrc + c);
            }
        }
        {   // Vt: 128 d-rows x 64 floats; 2 threads/row, 8 float4 each
            const int vrow = tid >> 1;
            const int vseg = tid & 1;
            const float* vsrc = vtbase + (size_t)vrow * S_LEN + kt * 64;
            uint32_t vd = smb + vs_off[s] + vrow * (FA_VT * 4);
#pragma unroll
            for (int i = 0; i < 8; i++) {
                int c = vseg * 4 + i * 8;
                CP_ASYNC16(vd + c * 4, vsrc + c);
            }
        }
        CP_COMMIT();
    };

    issue(0, 0);
    __syncthreads();   // Q ready

    float m_i[2] = {-1e30f, -1e30f};
    float l_i[2] = {0.f, 0.f};
    float O[16][4];
#pragma unroll
    for (int nt = 0; nt < 16; nt++)
#pragma unroll
        for (int r = 0; r < 4; r++) O[nt][r] = 0.f;

    const int qrow_base = wid * 16 + group;      // warp-local q rows (+0 / +8)

    for (int kt = 0; kt < ntiles; kt++) {
        const int s = kt & 1;
        if (kt + 1 < ntiles) { issue(kt + 1, s ^ 1); CP_WAIT(1); }
        else                 { CP_WAIT(0); }
        __syncthreads();

        const float* Kst = Ks[s];
        const float* Vst = Vs[s];

        // ---- S = Q K^T : 8 n-tiles of 8 keys, 16 k-steps over d ----
        float S[8][4];
#pragma unroll
        for (int nt = 0; nt < 8; nt++)
#pragma unroll
            for (int r = 0; r < 4; r++) S[nt][r] = 0.f;

#pragma unroll
        for (int ks = 0; ks < 16; ks++) {
            const int kk = ks * 8 + 2 * tig;
            uint32_t a[4];
            {
                uint2 v0 = *(const uint2*)&Qs[qrow_base * FA_QSTRIDE + kk];
                uint2 v1 = *(const uint2*)&Qs[(qrow_base + 8) * FA_QSTRIDE + kk];
                a[0] = v0.x;
                a[1] = v1.x;
                a[2] = v0.y;
                a[3] = v1.y;
            }
#pragma unroll
            for (int nt = 0; nt < 8; nt++) {
                uint2 w = *(const uint2*)&Kst[(nt * 8 + group) * FA_KSTRIDE + kk];
                uint32_t bfr[2] = { w.x, w.y };
                mma_tf32(S[nt], a, bfr);
            }
        }

        // ---- causal mask on boundary tiles ----
        if (kt >= 2 * qi) {
            const int q0 = qm0 + qrow_base;
            const int kbase_g = kt * 64 + 2 * tig;
#pragma unroll
            for (int nt = 0; nt < 8; nt++) {
                int k0 = kbase_g + nt * 8;
                if (k0 > q0)     S[nt][0] = -1e30f;
                if (k0 + 1 > q0) S[nt][1] = -1e30f;
                if (k0 > q0 + 8)     S[nt][2] = -1e30f;
                if (k0 + 1 > q0 + 8) S[nt][3] = -1e30f;
            }
        }

        // ---- online softmax (rows r0=qrow_base, r1=+8) ----
        float mx0 = -1e30f, mx1 = -1e30f;
#pragma unroll
        for (int nt = 0; nt < 8; nt++) {
            mx0 = fmaxf(mx0, fmaxf(S[nt][0], S[nt][1]));
            mx1 = fmaxf(mx1, fmaxf(S[nt][2], S[nt][3]));
        }
        mx0 = fmaxf(mx0, __shfl_xor_sync(0xffffffffu, mx0, 1));
        mx0 = fmaxf(mx0, __shfl_xor_sync(0xffffffffu, mx0, 2));
        mx1 = fmaxf(mx1, __shfl_xor_sync(0xffffffffu, mx1, 1));
        mx1 = fmaxf(mx1, __shfl_xor_sync(0xffffffffu, mx1, 2));

        float mn0 = fmaxf(m_i[0], mx0);
        float mn1 = fmaxf(m_i[1], mx1);
        float al0 = __expf(m_i[0] - mn0);
        float al1 = __expf(m_i[1] - mn1);
        m_i[0] = mn0; m_i[1] = mn1;

        float sum0 = 0.f, sum1 = 0.f;
#pragma unroll
        for (int nt = 0; nt < 8; nt++) {
            float p0 = __expf(S[nt][0] - mn0);
            float p1 = __expf(S[nt][1] - mn0);
            float p2 = __expf(S[nt][2] - mn1);
            float p3 = __expf(S[nt][3] - mn1);
            sum0 += p0 + p1;
            sum1 += p2 + p3;
            S[nt][0] = __uint_as_float(f2tf32(p0));
            S[nt][1] = __uint_as_float(f2tf32(p1));
            S[nt][2] = __uint_as_float(f2tf32(p2));
            S[nt][3] = __uint_as_float(f2tf32(p3));
        }
        sum0 += __shfl_xor_sync(0xffffffffu, sum0, 1);
        sum0 += __shfl_xor_sync(0xffffffffu, sum0, 2);
        sum1 += __shfl_xor_sync(0xffffffffu, sum1, 1);
        sum1 += __shfl_xor_sync(0xffffffffu, sum1, 2);
        l_i[0] = l_i[0] * al0 + sum0;
        l_i[1] = l_i[1] * al1 + sum1;

#pragma unroll
        for (int nt = 0; nt < 16; nt++) {
            O[nt][0] *= al0; O[nt][1] *= al0;
            O[nt][2] *= al1; O[nt][3] *= al1;
        }

        // ---- O += P V : P fragments = S accum (k-permuted); V from Vt ----
#pragma unroll
        for (int ks2 = 0; ks2 < 8; ks2++) {
            uint32_t a[4] = { __float_as_uint(S[ks2][0]), __float_as_uint(S[ks2][2]),
                              __float_as_uint(S[ks2][1]), __float_as_uint(S[ks2][3]) };
            const int vrow = ks2 * 8 + 2 * tig;
#pragma unroll
            for (int nt = 0; nt < 16; nt++) {
                uint2 w = *(const uint2*)&Vst[(nt * 8 + group) * FA_VT + vrow];
                uint32_t bfr[2] = { w.x, w.y };
                mma_tf32(O[nt], a, bfr);
            }
        }
        __syncthreads();   // all warps done with stage s before it is re-filled
    }

    // ---- epilogue ----
    float inv0 = 1.f / l_i[0];
    float inv1 = 1.f / l_i[1];
    const size_t orow0 = (size_t)(b * S_LEN + qm0 + qrow_base) * Q_SIZE + h * HEAD_DIM;
    const size_t orow1 = orow0 + 8 * Q_SIZE;
#pragma unroll
    for (int nt = 0; nt < 16; nt++) {
        int nc = nt * 8 + 2 * tig;
        *(float2*)&attn_out[orow0 + nc] = make_float2(O[nt][0] * inv0, O[nt][1] * inv0);
        *(float2*)&attn_out[orow1 + nc] = make_float2(O[nt][2] * inv1, O[nt][3] * inv1);
    }
}

// ---------------------------------------------------------------------------
extern "C" void kernel_launch(void* const* d_in, const int* in_sizes, int n_in,
                              void* d_out, int out_size)
{
    const float* hidden    = (const float*)d_in[0];
    const int*   positions = (const int*)d_in[1];
    const float* w_qkv     = (const float*)d_in[2];
    const float* w_o       = (const float*)d_in[3];
    const float* q_norm_w  = (const float*)d_in[4];
    const float* k_norm_w  = (const float*)d_in[5];
    float* out = (float*)d_out;

    float* qkv;
    float* attn;
    float* vt;
    cudaGetSymbolAddress((void**)&qkv, g_qkv);
    cudaGetSymbolAddress((void**)&attn, g_attn);
    cudaGetSymbolAddress((void**)&vt, g_vt);

    cudaFuncSetAttribute(gemm_tc, cudaFuncAttributeMaxDynamicSharedMemorySize, GEMM_SMEM);
    cudaFuncSetAttribute(flash_tc, cudaFuncAttributeMaxDynamicSharedMemorySize, FA_SMEM);

    // 1) QKV projection (tf32 mma.sync)
    gemm_tc<<<dim3(QKV_DIM / GBN, TOKENS / GBM), 256, GEMM_SMEM>>>(
        hidden, w_qkv, qkv, TOKENS, QKV_DIM, HIDDEN);

    // 2) RMSNorm + RoPE (K pre-rounded to tf32)
    norm_rope<<<TOKENS * (N_HEADS + N_KV), 128>>>(qkv, positions, q_norm_w, k_norm_w);

    // 2b) V transpose + tf32 round
    transpose_v<<<dim3(S_LEN / 32, B_SZ * N_KV * (HEAD_DIM / 32)), 256>>>(qkv, vt);

    // 3) Causal flash attention (tf32 mma.sync)
    flash_tc<<<dim3(S_LEN / 128, B_SZ * N_HEADS), 256, FA_SMEM>>>(qkv, vt, attn);

    // 4) Output projection (tf32 mma.sync)
    gemm_tc<<<dim3(HIDDEN / GBN, TOKENS / GBM), 256, GEMM_SMEM>>>(
        attn, w_o, out, TOKENS, HIDDEN, Q_SIZE);
}

// round 9
// speedup vs baseline: 1.6754x; 1.5468x over previous
#include <cuda_runtime.h>
#include <cuda_bf16.h>
#include <math.h>
#include <cstdint>

#define HIDDEN 2048
#define N_HEADS 32
#define N_KV 4
#define HEAD_DIM 128
#define B_SZ 2
#define S_LEN 2048
#define TOKENS (B_SZ * S_LEN)            // 4096
#define QKV_DIM ((N_HEADS + 2 * N_KV) * HEAD_DIM)  // 5120
#define Q_SIZE (N_HEADS * HEAD_DIM)      // 4096
#define KV_SIZE (N_KV * HEAD_DIM)        // 512

// Scratch
__device__ float g_qkv[(size_t)TOKENS * QKV_DIM];              // ~84 MB
__device__ float g_attn[(size_t)TOKENS * Q_SIZE];              // ~67 MB (tf32-rounded by flash)
__device__ float g_vt[(size_t)B_SZ * N_KV * HEAD_DIM * S_LEN]; // 8 MB, tf32 V^T
__device__ float g_hid_r[(size_t)TOKENS * HIDDEN];             // 34 MB, tf32 hidden
__device__ float g_wqkv_r[(size_t)QKV_DIM * HIDDEN];           // 42 MB, tf32 w_qkv
__device__ float g_wo_r[(size_t)HIDDEN * Q_SIZE];              // 34 MB, tf32 w_o

// ---------------------------------------------------------------------------
// Helpers
// ---------------------------------------------------------------------------
static __device__ __forceinline__ uint32_t smem_u32(const void* p) {
    uint32_t a;
    asm("{ .reg .u64 t; cvta.to.shared.u64 t, %1; cvt.u32.u64 %0, t; }" : "=r"(a) : "l"(p));
    return a;
}
static __device__ __forceinline__ uint32_t f2tf32(float x) {
    uint32_t r;
    asm("cvt.rna.tf32.f32 %0, %1;" : "=r"(r) : "f"(x));
    return r;
}
#define CP_ASYNC16(dst, src) \
    asm volatile("cp.async.cg.shared.global [%0], [%1], 16;" :: "r"(dst), "l"(src) : "memory")
#define CP_COMMIT() asm volatile("cp.async.commit_group;" ::: "memory")
#define CP_WAIT(n)  asm volatile("cp.async.wait_group %0;" :: "n"(n) : "memory")

// m16n8k8 tf32 mma.sync (row.col): D += A * B
static __device__ __forceinline__ void mma_tf32(
    float* c, const uint32_t* a, const uint32_t* b)
{
    asm volatile(
        "mma.sync.aligned.m16n8k8.row.col.f32.tf32.tf32.f32 "
        "{%0,%1,%2,%3}, {%4,%5,%6,%7}, {%8,%9}, {%0,%1,%2,%3};"
        : "+f"(c[0]), "+f"(c[1]), "+f"(c[2]), "+f"(c[3])
        : "r"(a[0]), "r"(a[1]), "r"(a[2]), "r"(a[3]), "r"(b[0]), "r"(b[1]));
}

// ---------------------------------------------------------------------------
// Elementwise tf32 rounding (float4-vectorized)
// ---------------------------------------------------------------------------
__global__ __launch_bounds__(256) void round_tf32_k(
    const float4* __restrict__ in, float4* __restrict__ out, int n4)
{
    int i = blockIdx.x * 256 + threadIdx.x;
    if (i < n4) {
        float4 v = in[i];
        out[i] = make_float4(
            __uint_as_float(f2tf32(v.x)), __uint_as_float(f2tf32(v.y)),
            __uint_as_float(f2tf32(v.z)), __uint_as_float(f2tf32(v.w)));
    }
}

// ---------------------------------------------------------------------------
// tf32 mma.sync GEMM on PRE-ROUNDED inputs (no cvt in the hot loop):
// C[M,N] = A[M,K] * B[N,K]^T (row-major, K contiguous)
// ---------------------------------------------------------------------------
#define GBM 128
#define GBN 128
#define GBK 32
#define KPAD 40
#define STAGE_FLOATS ((GBM + GBN) * KPAD)
#define STAGE_BYTES (STAGE_FLOATS * 4)
#define GEMM_SMEM (2 * STAGE_BYTES)

__global__ __launch_bounds__(256) void gemm_tc(
    const float* __restrict__ A, const float* __restrict__ Bw,
    float* __restrict__ C, int M, int N, int K)
{
    extern __shared__ float smf[];
    const uint32_t smb = smem_u32(smf);
    const int tid = threadIdx.x;
    const int wid = tid >> 5;
    const int lane = tid & 31;
    const int group = lane >> 2;
    const int tig = lane & 3;
    const int wm = wid >> 2;
    const int wn = wid & 3;
    const int m0 = blockIdx.y * GBM;
    const int n0 = blockIdx.x * GBN;

    const int lrow = tid >> 3;
    const int lseg = tid & 7;

    float acc[4][4][4];
#pragma unroll
    for (int mt = 0; mt < 4; mt++)
#pragma unroll
        for (int nt = 0; nt < 4; nt++)
#pragma unroll
            for (int r = 0; r < 4; r++) acc[mt][nt][r] = 0.f;

    const int chunks = K / GBK;

    auto issue = [&](int c, int s) {
        const uint32_t sa = smb + s * STAGE_BYTES;
        const uint32_t sb = sa + GBM * KPAD * 4;
        const float* Ab = A + (size_t)m0 * K + (size_t)c * GBK;
        const float* Bb = Bw + (size_t)n0 * K + (size_t)c * GBK;
#pragma unroll
        for (int i = 0; i < 4; i++) {
            int row = lrow + i * 32;
            CP_ASYNC16(sa + row * (KPAD * 4) + lseg * 16,
                       Ab + (size_t)row * K + lseg * 4);
            CP_ASYNC16(sb + row * (KPAD * 4) + lseg * 16,
                       Bb + (size_t)row * K + lseg * 4);
        }
        CP_COMMIT();
    };

    issue(0, 0);

    for (int c = 0; c < chunks; c++) {
        const int s = c & 1;
        if (c + 1 < chunks) { issue(c + 1, s ^ 1); CP_WAIT(1); }
        else                { CP_WAIT(0); }
        __syncthreads();

        const float* As = smf + s * STAGE_FLOATS;
        const float* Bs = As + GBM * KPAD;

#pragma unroll
        for (int ks = 0; ks < 4; ks++) {
            const int kk = ks * 8 + 2 * tig;
            uint32_t a[4][4], b[4][2];
#pragma unroll
            for (int mt = 0; mt < 4; mt++) {
                int mr = wm * 64 + mt * 16 + group;
                uint2 v0 = *(const uint2*)&As[mr * KPAD + kk];
                uint2 v1 = *(const uint2*)&As[(mr + 8) * KPAD + kk];
                a[mt][0] = v0.x;
                a[mt][2] = v0.y;
                a[mt][1] = v1.x;
                a[mt][3] = v1.y;
            }
#pragma unroll
            for (int nt = 0; nt < 4; nt++) {
                int nr = wn * 32 + nt * 8 + group;
                uint2 v = *(const uint2*)&Bs[nr * KPAD + kk];
                b[nt][0] = v.x;
                b[nt][1] = v.y;
            }
#pragma unroll
            for (int mt = 0; mt < 4; mt++)
#pragma unroll
                for (int nt = 0; nt < 4; nt++)
                    mma_tf32(acc[mt][nt], a[mt], b[nt]);
        }
        __syncthreads();
    }

#pragma unroll
    for (int mt = 0; mt < 4; mt++) {
        int mr = m0 + wm * 64 + mt * 16 + group;
#pragma unroll
        for (int nt = 0; nt < 4; nt++) {
            int nc = n0 + wn * 32 + nt * 8 + 2 * tig;
            *(float2*)&C[(size_t)mr * N + nc] =
                make_float2(acc[mt][nt][0], acc[mt][nt][1]);
            *(float2*)&C[(size_t)(mr + 8) * N + nc] =
                make_float2(acc[mt][nt][2], acc[mt][nt][3]);
        }
    }
}

// ---------------------------------------------------------------------------
// Fused RMSNorm + RoPE: one block per token (128 threads), warp-per-head.
// fp32 sincos table computed once per token. K heads tf32-pre-rounded.
// ---------------------------------------------------------------------------
__global__ __launch_bounds__(128) void norm_rope(
    float* __restrict__ qkv, const int* __restrict__ positions,
    const float* __restrict__ qw, const float* __restrict__ kw)
{
    const int t = blockIdx.x;
    const int tid = threadIdx.x;
    const int wid = tid >> 5;
    const int lane = tid & 31;
    __shared__ float cs[64], sn[64], wqs[128], wks[128];

    if (tid < 64) {
        int pos = positions[t];
        // inv_freq = theta^(-i/64); log2(1e6) = 19.931568569324174
        float invf = exp2f(-(float)tid * (19.931568569324174f / 64.0f));
        float ang = (float)pos * invf;
        float s, c;
        sincosf(ang, &s, &c);
        cs[tid] = c;
        sn[tid] = s;
    }
    wqs[tid] = qw[tid];
    wks[tid] = kw[tid];
    __syncthreads();

    float* base = qkv + (size_t)t * QKV_DIM;
#pragma unroll
    for (int i = 0; i < 9; i++) {
        const int hh = wid * 9 + i;                 // 0..35
        const bool is_k = hh >= N_HEADS;
        float* ptr = is_k ? base + Q_SIZE + (hh - N_HEADS) * HEAD_DIM
                          : base + hh * HEAD_DIM;
        const float* w = is_k ? wks : wqs;

        float4 x = *(float4*)&ptr[lane * 4];
        float ss = x.x * x.x + x.y * x.y + x.z * x.z + x.w * x.w;
#pragma unroll
        for (int o = 16; o > 0; o >>= 1) ss += __shfl_xor_sync(0xffffffffu, ss, o);
        float r = rsqrtf(ss * (1.0f / 128.0f) + 1e-6f);

        float4 wv = *(const float4*)&w[lane * 4];
        float v0 = x.x * r * wv.x;
        float v1 = x.y * r * wv.y;
        float v2 = x.z * r * wv.z;
        float v3 = x.w * r * wv.w;

        // RoPE partner exchange: lanes 0-15 hold x1, 16-31 hold x2 (same freq idx)
        float p0 = __shfl_xor_sync(0xffffffffu, v0, 16);
        float p1 = __shfl_xor_sync(0xffffffffu, v1, 16);
        float p2 = __shfl_xor_sync(0xffffffffu, v2, 16);
        float p3 = __shfl_xor_sync(0xffffffffu, v3, 16);
        const int fi = (lane & 15) * 4;
        float o0, o1, o2, o3;
        if (lane < 16) {
            o0 = v0 * cs[fi + 0] - p0 * sn[fi + 0];
            o1 = v1 * cs[fi + 1] - p1 * sn[fi + 1];
            o2 = v2 * cs[fi + 2] - p2 * sn[fi + 2];
            o3 = v3 * cs[fi + 3] - p3 * sn[fi + 3];
        } else {
            o0 = v0 * cs[fi + 0] + p0 * sn[fi + 0];
            o1 = v1 * cs[fi + 1] + p1 * sn[fi + 1];
            o2 = v2 * cs[fi + 2] + p2 * sn[fi + 2];
            o3 = v3 * cs[fi + 3] + p3 * sn[fi + 3];
        }
        if (is_k) {
            o0 = __uint_as_float(f2tf32(o0));
            o1 = __uint_as_float(f2tf32(o1));
            o2 = __uint_as_float(f2tf32(o2));
            o3 = __uint_as_float(f2tf32(o3));
        }
        *(float4*)&ptr[lane * 4] = make_float4(o0, o1, o2, o3);
    }
}

// ---------------------------------------------------------------------------
// V transpose + tf32 round: g_vt[((b*N_KV+kvh)*HEAD_DIM + d)*S_LEN + s]
// ---------------------------------------------------------------------------
__global__ __launch_bounds__(256) void transpose_v(
    const float* __restrict__ qkv, float* __restrict__ vt)
{
    __shared__ float tile[32][33];
    const int sb = blockIdx.x * 32;
    int rest = blockIdx.y;                 // = b*16 + kvh*4 + dt
    const int dt = rest & 3; rest >>= 2;
    const int kvh = rest & 3; rest >>= 2;
    const int b = rest;
    const int tx = threadIdx.x & 31;
    const int ty = threadIdx.x >> 5;       // 0..7

    const float* src = qkv + (size_t)(b * S_LEN + sb) * QKV_DIM
                     + Q_SIZE + KV_SIZE + kvh * HEAD_DIM + dt * 32;
#pragma unroll
    for (int i = 0; i < 4; i++) {
        int s = ty + i * 8;
        tile[s][tx] = src[(size_t)s * QKV_DIM + tx];
    }
    __syncthreads();
    float* dst = vt + ((size_t)(b * N_KV + kvh) * HEAD_DIM + dt * 32) * S_LEN + sb;
#pragma unroll
    for (int i = 0; i < 4; i++) {
        int d = ty + i * 8;
        dst[(size_t)d * S_LEN + tx] = __uint_as_float(f2tf32(tile[tx][d]));
    }
}

// ---------------------------------------------------------------------------
// Tensor-core flash attention (tf32 mma.sync), causal, GQA group 8.
// CTA: 128 q-rows of one (b,h), 256 threads / 8 warps. Key tile 64.
// K (pre-rounded, row-major) and Vt (pre-rounded, [d][s]) double-buffered.
// Epilogue writes tf32-rounded output (feeds the pre-rounded out-proj GEMM).
// ---------------------------------------------------------------------------
#define FA_QSTRIDE 136
#define FA_KSTRIDE 136
#define FA_VT 72
#define FA_Q_FLOATS (128 * FA_QSTRIDE)
#define FA_K_FLOATS (64 * FA_KSTRIDE)
#define FA_V_FLOATS (128 * FA_VT)
#define FA_SMEM ((FA_Q_FLOATS + 2 * FA_K_FLOATS + 2 * FA_V_FLOATS) * 4)

__global__ __launch_bounds__(256, 1) void flash_tc(
    const float* __restrict__ qkv, const float* __restrict__ vt,
    float* __restrict__ attn_out)
{
    extern __shared__ float smf[];
    float* Qs = smf;
    float* Ks[2] = { Qs + FA_Q_FLOATS, Qs + FA_Q_FLOATS + FA_K_FLOATS };
    float* Vs[2] = { Qs + FA_Q_FLOATS + 2 * FA_K_FLOATS,
                     Qs + FA_Q_FLOATS + 2 * FA_K_FLOATS + FA_V_FLOATS };
    const uint32_t smb = smem_u32(smf);
    const uint32_t ks_off[2] = { (uint32_t)(FA_Q_FLOATS * 4),
                                 (uint32_t)((FA_Q_FLOATS + FA_K_FLOATS) * 4) };
    const uint32_t vs_off[2] = { (uint32_t)((FA_Q_FLOATS + 2 * FA_K_FLOATS) * 4),
                                 (uint32_t)((FA_Q_FLOATS + 2 * FA_K_FLOATS + FA_V_FLOATS) * 4) };

    const int qi = (int)(gridDim.x - 1 - blockIdx.x);
    const int bh = blockIdx.y;
    const int b = bh >> 5;
    const int h = bh & 31;
    const int kvh = h >> 3;
    const int tid = threadIdx.x;
    const int wid = tid >> 5;
    const int lane = tid & 31;
    const int group = lane >> 2;
    const int tig = lane & 3;
    const int qm0 = qi * 128;
    const float scale = 0.08838834764831845f;

    const float* qbase = qkv + (size_t)(b * S_LEN + qm0) * QKV_DIM + h * HEAD_DIM;
#pragma unroll
    for (int i = 0; i < 16; i++) {
        int f = tid + i * 256;
        int row = f >> 5, c4 = f & 31;
        float4 v = *(const float4*)&qbase[(size_t)row * QKV_DIM + c4 * 4];
        float* d = &Qs[row * FA_QSTRIDE + c4 * 4];
        d[0] = __uint_as_float(f2tf32(v.x * scale));
        d[1] = __uint_as_float(f2tf32(v.y * scale));
        d[2] = __uint_as_float(f2tf32(v.z * scale));
        d[3] = __uint_as_float(f2tf32(v.w * scale));
    }

    const float* kbase = qkv + (size_t)(b * S_LEN) * QKV_DIM + Q_SIZE + kvh * HEAD_DIM;
    const float* vtbase = vt + (size_t)(b * N_KV + kvh) * HEAD_DIM * S_LEN;
    const int ntiles = 2 * qi + 2;

    auto issue = [&](int kt, int s) {
        {
            const int lrow = tid >> 2;
            const int lseg = tid & 3;
            const float* ksrc = kbase + (size_t)(kt * 64 + lrow) * QKV_DIM;
            uint32_t kd = smb + ks_off[s] + lrow * (FA_KSTRIDE * 4);
#pragma unroll
            for (int i = 0; i < 8; i++) {
                int c = lseg * 4 + i * 16;
                CP_ASYNC16(kd + c * 4, ksrc + c);
            }
        }
        {
            const int vrow = tid >> 1;
            const int vseg = tid & 1;
            const float* vsrc = vtbase + (size_t)vrow * S_LEN + kt * 64;
            uint32_t vd = smb + vs_off[s] + vrow * (FA_VT * 4);
#pragma unroll
            for (int i = 0; i < 8; i++) {
                int c = vseg * 4 + i * 8;
                CP_ASYNC16(vd + c * 4, vsrc + c);
            }
        }
        CP_COMMIT();
    };

    issue(0, 0);
    __syncthreads();

    float m_i[2] = {-1e30f, -1e30f};
    float l_i[2] = {0.f, 0.f};
    float O[16][4];
#pragma unroll
    for (int nt = 0; nt < 16; nt++)
#pragma unroll
        for (int r = 0; r < 4; r++) O[nt][r] = 0.f;

    const int qrow_base = wid * 16 + group;

    for (int kt = 0; kt < ntiles; kt++) {
        const int s = kt & 1;
        if (kt + 1 < ntiles) { issue(kt + 1, s ^ 1); CP_WAIT(1); }
        else                 { CP_WAIT(0); }
        __syncthreads();

        const float* Kst = Ks[s];
        const float* Vst = Vs[s];

        float S[8][4];
#pragma unroll
        for (int nt = 0; nt < 8; nt++)
#pragma unroll
            for (int r = 0; r < 4; r++) S[nt][r] = 0.f;

#pragma unroll
        for (int ks = 0; ks < 16; ks++) {
            const int kk = ks * 8 + 2 * tig;
            uint32_t a[4];
            {
                uint2 v0 = *(const uint2*)&Qs[qrow_base * FA_QSTRIDE + kk];
                uint2 v1 = *(const uint2*)&Qs[(qrow_base + 8) * FA_QSTRIDE + kk];
                a[0] = v0.x;
                a[1] = v1.x;
                a[2] = v0.y;
                a[3] = v1.y;
            }
#pragma unroll
            for (int nt = 0; nt < 8; nt++) {
                uint2 w = *(const uint2*)&Kst[(nt * 8 + group) * FA_KSTRIDE + kk];
                uint32_t bfr[2] = { w.x, w.y };
                mma_tf32(S[nt], a, bfr);
            }
        }

        if (kt >= 2 * qi) {
            const int q0 = qm0 + qrow_base;
            const int kbase_g = kt * 64 + 2 * tig;
#pragma unroll
            for (int nt = 0; nt < 8; nt++) {
                int k0 = kbase_g + nt * 8;
                if (k0 > q0)     S[nt][0] = -1e30f;
                if (k0 + 1 > q0) S[nt][1] = -1e30f;
                if (k0 > q0 + 8)     S[nt][2] = -1e30f;
                if (k0 + 1 > q0 + 8) S[nt][3] = -1e30f;
            }
        }

        float mx0 = -1e30f, mx1 = -1e30f;
#pragma unroll
        for (int nt = 0; nt < 8; nt++) {
            mx0 = fmaxf(mx0, fmaxf(S[nt][0], S[nt][1]));
            mx1 = fmaxf(mx1, fmaxf(S[nt][2], S[nt][3]));
        }
        mx0 = fmaxf(mx0, __shfl_xor_sync(0xffffffffu, mx0, 1));
        mx0 = fmaxf(mx0, __shfl_xor_sync(0xffffffffu, mx0, 2));
        mx1 = fmaxf(mx1, __shfl_xor_sync(0xffffffffu, mx1, 1));
        mx1 = fmaxf(mx1, __shfl_xor_sync(0xffffffffu, mx1, 2));

        float mn0 = fmaxf(m_i[0], mx0);
        float mn1 = fmaxf(m_i[1], mx1);
        float al0 = __expf(m_i[0] - mn0);
        float al1 = __expf(m_i[1] - mn1);
        m_i[0] = mn0; m_i[1] = mn1;

        float sum0 = 0.f, sum1 = 0.f;
#pragma unroll
        for (int nt = 0; nt < 8; nt++) {
            float p0 = __expf(S[nt][0] - mn0);
            float p1 = __expf(S[nt][1] - mn0);
            float p2 = __expf(S[nt][2] - mn1);
            float p3 = __expf(S[nt][3] - mn1);
            sum0 += p0 + p1;
            sum1 += p2 + p3;
            S[nt][0] = __uint_as_float(f2tf32(p0));
            S[nt][1] = __uint_as_float(f2tf32(p1));
            S[nt][2] = __uint_as_float(f2tf32(p2));
            S[nt][3] = __uint_as_float(f2tf32(p3));
        }
        sum0 += __shfl_xor_sync(0xffffffffu, sum0, 1);
        sum0 += __shfl_xor_sync(0xffffffffu, sum0, 2);
        sum1 += __shfl_xor_sync(0xffffffffu, sum1, 1);
        sum1 += __shfl_xor_sync(0xffffffffu, sum1, 2);
        l_i[0] = l_i[0] * al0 + sum0;
        l_i[1] = l_i[1] * al1 + sum1;

#pragma unroll
        for (int nt = 0; nt < 16; nt++) {
            O[nt][0] *= al0; O[nt][1] *= al0;
            O[nt][2] *= al1; O[nt][3] *= al1;
        }

#pragma unroll
        for (int ks2 = 0; ks2 < 8; ks2++) {
            uint32_t a[4] = { __float_as_uint(S[ks2][0]), __float_as_uint(S[ks2][2]),
                              __float_as_uint(S[ks2][1]), __float_as_uint(S[ks2][3]) };
            const int vrow = ks2 * 8 + 2 * tig;
#pragma unroll
            for (int nt = 0; nt < 16; nt++) {
                uint2 w = *(const uint2*)&Vst[(nt * 8 + group) * FA_VT + vrow];
                uint32_t bfr[2] = { w.x, w.y };
                mma_tf32(O[nt], a, bfr);
            }
        }
        __syncthreads();
    }

    // ---- epilogue (tf32-rounded for the pre-rounded out-proj GEMM) ----
    float inv0 = 1.f / l_i[0];
    float inv1 = 1.f / l_i[1];
    const size_t orow0 = (size_t)(b * S_LEN + qm0 + qrow_base) * Q_SIZE + h * HEAD_DIM;
    const size_t orow1 = orow0 + 8 * Q_SIZE;
#pragma unroll
    for (int nt = 0; nt < 16; nt++) {
        int nc = nt * 8 + 2 * tig;
        *(float2*)&attn_out[orow0 + nc] = make_float2(
            __uint_as_float(f2tf32(O[nt][0] * inv0)),
            __uint_as_float(f2tf32(O[nt][1] * inv0)));
        *(float2*)&attn_out[orow1 + nc] = make_float2(
            __uint_as_float(f2tf32(O[nt][2] * inv1)),
            __uint_as_float(f2tf32(O[nt][3] * inv1)));
    }
}

// ---------------------------------------------------------------------------
extern "C" void kernel_launch(void* const* d_in, const int* in_sizes, int n_in,
                              void* d_out, int out_size)
{
    const float* hidden    = (const float*)d_in[0];
    const int*   positions = (const int*)d_in[1];
    const float* w_qkv     = (const float*)d_in[2];
    const float* w_o       = (const float*)d_in[3];
    const float* q_norm_w  = (const float*)d_in[4];
    const float* k_norm_w  = (const float*)d_in[5];
    float* out = (float*)d_out;

    float *qkv, *attn, *vt, *hid_r, *wqkv_r, *wo_r;
    cudaGetSymbolAddress((void**)&qkv, g_qkv);
    cudaGetSymbolAddress((void**)&attn, g_attn);
    cudaGetSymbolAddress((void**)&vt, g_vt);
    cudaGetSymbolAddress((void**)&hid_r, g_hid_r);
    cudaGetSymbolAddress((void**)&wqkv_r, g_wqkv_r);
    cudaGetSymbolAddress((void**)&wo_r, g_wo_r);

    cudaFuncSetAttribute(gemm_tc, cudaFuncAttributeMaxDynamicSharedMemorySize, GEMM_SMEM);
    cudaFuncSetAttribute(flash_tc, cudaFuncAttributeMaxDynamicSharedMemorySize, FA_SMEM);

    // 0) Pre-round GEMM operands to tf32
    {
        int n4h = TOKENS * HIDDEN / 4;
        round_tf32_k<<<(n4h + 255) / 256, 256>>>((const float4*)hidden, (float4*)hid_r, n4h);
        int n4q = QKV_DIM * HIDDEN / 4;
        round_tf32_k<<<(n4q + 255) / 256, 256>>>((const float4*)w_qkv, (float4*)wqkv_r, n4q);
        int n4o = HIDDEN * Q_SIZE / 4;
        round_tf32_k<<<(n4o + 255) / 256, 256>>>((const float4*)w_o, (float4*)wo_r, n4o);
    }

    // 1) QKV projection (cvt-free tf32 mma.sync)
    gemm_tc<<<dim3(QKV_DIM / GBN, TOKENS / GBM), 256, GEMM_SMEM>>>(
        hid_r, wqkv_r, qkv, TOKENS, QKV_DIM, HIDDEN);

    // 2) Fused RMSNorm + RoPE (one block per token; K pre-rounded to tf32)
    norm_rope<<<TOKENS, 128>>>(qkv, positions, q_norm_w, k_norm_w);

    // 2b) V transpose + tf32 round
    transpose_v<<<dim3(S_LEN / 32, B_SZ * N_KV * (HEAD_DIM / 32)), 256>>>(qkv, vt);

    // 3) Causal flash attention (tf32 mma.sync)
    flash_tc<<<dim3(S_LEN / 128, B_SZ * N_HEADS), 256, FA_SMEM>>>(qkv, vt, attn);

    // 4) Output projection (cvt-free tf32 mma.sync)
    gemm_tc<<<dim3(HIDDEN / GBN, TOKENS / GBM), 256, GEMM_SMEM>>>(
        attn, wo_r, out, TOKENS, HIDDEN, Q_SIZE);
}